// round 14
// baseline (speedup 1.0000x reference)
#include <cuda_runtime.h>
#include <cuda_bf16.h>
#include <cstdint>

#define BB 8
#define CC 64
#define HWSZ (152 * 272)     // 41344
#define KK 500
#define KPAD 512
#define NSLOTS 32
#define NLBLK 512            // 8x8 tiles x 8 batches

#define ALPHA 0.25f
#define PROB_MIN 1e-4f

// Scratch (no allocations allowed)
__device__ __align__(16) __nv_bfloat16 g_curb[BB * KPAD * CC];
__device__ __align__(16) __nv_bfloat16 g_preb[BB * KPAD * CC];
__device__ double   g_accs[NSLOTS];   // zero-init; last block resets
__device__ unsigned g_count = 0;

__device__ __forceinline__ uint32_t smem_u32(const void* p) {
    uint32_t a;
    asm("{ .reg .u64 t; cvta.to.shared.u64 t, %1; cvt.u32.u64 %0, t; }"
        : "=r"(a) : "l"(p));
    return a;
}
__device__ __forceinline__ void ldsm_x4(uint32_t& r0, uint32_t& r1,
                                        uint32_t& r2, uint32_t& r3,
                                        uint32_t addr) {
    asm volatile("ldmatrix.sync.aligned.m8n8.x4.shared.b16 {%0,%1,%2,%3}, [%4];"
                 : "=r"(r0), "=r"(r1), "=r"(r2), "=r"(r3) : "r"(addr));
}
__device__ __forceinline__ void ldsm_x2(uint32_t& r0, uint32_t& r1,
                                        uint32_t addr) {
    asm volatile("ldmatrix.sync.aligned.m8n8.x2.shared.b16 {%0,%1}, [%2];"
                 : "=r"(r0), "=r"(r1) : "r"(addr));
}
__device__ __forceinline__ void mma_16816(float* c, const uint32_t* a,
                                          const uint32_t* b) {
    asm volatile(
        "mma.sync.aligned.m16n8k16.row.col.f32.bf16.bf16.f32 "
        "{%0,%1,%2,%3}, {%4,%5,%6,%7}, {%8,%9}, {%0,%1,%2,%3};"
        : "+f"(c[0]), "+f"(c[1]), "+f"(c[2]), "+f"(c[3])
        : "r"(a[0]), "r"(a[1]), "r"(a[2]), "r"(a[3]), "r"(b[0]), "r"(b[1]));
}

// ---------------------------------------------------------------------------
// Gather + bf16 convert: 2 channels/thread, 512 blocks (4096 warps) to
// maximize chip-wide outstanding-LDG (per-warp cap M_max~55 makes MLP
// warp-count-limited). Inline int64/int32 index-dtype detection.
// ---------------------------------------------------------------------------
__global__ __launch_bounds__(256)
void gather_kernel(const float* __restrict__ cur_reid,
                   const float* __restrict__ pre_reid,
                   const void*  __restrict__ cur_inds,
                   const void*  __restrict__ pre_inds,
                   const void*  __restrict__ cur_cir,
                   const void*  __restrict__ pre_cir,
                   const int*   __restrict__ mask)
{
    __shared__ int s64;
    if (threadIdx.x < 32) {
        long long v = ((const long long*)cur_inds)[threadIdx.x];
        unsigned bad = __ballot_sync(0xffffffffu,
                                     (v < 0) || (v >= (long long)HWSZ));
        if (threadIdx.x == 0) s64 = (bad == 0);
    }
    __syncthreads();

    int tid = blockIdx.x * 256 + threadIdx.x;     // one bf16x2 pair each
    if (tid >= BB * KPAD * 32) return;
    int c2  = tid & 31;            // channel pair: c = 2*c2, 2*c2+1
    int bk  = tid >> 5;            // b*512 + row
    int b   = bk >> 9;
    int row = bk & (KPAD - 1);

    __nv_bfloat162* dstC = (__nv_bfloat162*)g_curb;
    __nv_bfloat162* dstP = (__nv_bfloat162*)g_preb;

    if (row >= KK) {
        __nv_bfloat162 z;
        z.x = __float2bfloat16(0.0f); z.y = z.x;
        dstC[tid] = z;
        dstP[tid] = z;
        return;
    }
    int mk = b * KK + row;
    int m  = mask[mk];
    int ic, ip;
    if (s64) {
        ic = (int)(m ? ((const long long*)cur_inds)[mk]
                     : ((const long long*)cur_cir)[mk]);
        ip = (int)(m ? ((const long long*)pre_inds)[mk]
                     : ((const long long*)pre_cir)[mk]);
    } else {
        ic = m ? ((const int*)cur_inds)[mk] : ((const int*)cur_cir)[mk];
        ip = m ? ((const int*)pre_inds)[mk] : ((const int*)pre_cir)[mk];
    }
    size_t base = ((size_t)b * CC + 2 * c2) * (size_t)HWSZ;
    float c0 = cur_reid[base + ic];
    float c1 = cur_reid[base + HWSZ + ic];
    float p0 = pre_reid[base + ip];
    float p1 = pre_reid[base + HWSZ + ip];
    __nv_bfloat162 vc, vp;
    vc.x = __float2bfloat16(c0); vc.y = __float2bfloat16(c1);
    vp.x = __float2bfloat16(p0); vp.y = __float2bfloat16(p1);
    dstC[tid] = vc;
    dstP[tid] = vp;
}

// ---------------------------------------------------------------------------
// HMMA loss kernel (champion structure, breadth-first epilogue, inline
// last-block finalize). 64x64 tile/block, grid (8,8,8)=512, 8 warps of
// 32x16 warp tiles.
// ---------------------------------------------------------------------------
__global__ __launch_bounds__(256)
void loss_kernel(const int* __restrict__ mask, float* __restrict__ out)
{
    __shared__ __align__(128) uint8_t smA[64 * 128];
    __shared__ __align__(128) uint8_t smB[64 * 128];
    __shared__ float wsum[8];

    int t   = threadIdx.x;
    int w   = t >> 5;
    int lid = t & 31;
    int b   = blockIdx.z;
    int it  = blockIdx.y;
    int jt  = blockIdx.x;
    int i0  = it * 64;
    int j0  = jt * 64;

    const uint4* srcA = (const uint4*)(g_curb + ((size_t)b * KPAD + i0) * CC);
    const uint4* srcB = (const uint4*)(g_preb + ((size_t)b * KPAD + j0) * CC);
    #pragma unroll
    for (int k = 0; k < 2; k++) {
        int u  = t + 256 * k;
        int r  = u >> 3;
        int c  = u & 7;
        int sw = (r << 7) + ((c ^ (r & 7)) << 4);
        *(uint4*)(smA + sw) = srcA[u];
        *(uint4*)(smB + sw) = srcB[u];
    }
    __syncthreads();

    uint32_t baseA = smem_u32(smA);
    uint32_t baseB = smem_u32(smB);

    int wm = w & 1;
    int wn = w >> 1;

    float acc[2][2][4] = {};
    #pragma unroll
    for (int ks = 0; ks < 4; ks++) {
        int kc = ks * 2;
        uint32_t a[2][4];
        #pragma unroll
        for (int fm = 0; fm < 2; fm++) {
            int row = wm * 32 + fm * 16 + (lid & 7) + ((lid >> 3) & 1) * 8;
            int ch  = kc + (lid >> 4);
            uint32_t addr = baseA + (row << 7) + ((ch ^ (row & 7)) << 4);
            ldsm_x4(a[fm][0], a[fm][1], a[fm][2], a[fm][3], addr);
        }
        uint32_t bf[2][2];
        #pragma unroll
        for (int fn = 0; fn < 2; fn++) {
            int l8  = lid & 15;
            int row = wn * 16 + fn * 8 + (l8 & 7);
            int ch  = kc + (l8 >> 3);
            uint32_t addr = baseB + (row << 7) + ((ch ^ (row & 7)) << 4);
            ldsm_x2(bf[fn][0], bf[fn][1], addr);
        }
        #pragma unroll
        for (int fm = 0; fm < 2; fm++)
            #pragma unroll
            for (int fn = 0; fn < 2; fn++)
                mma_16816(acc[fm][fn], a[fm], bf[fn]);
    }

    // ---------------- breadth-first epilogue ----------------
    int gid = lid >> 2;
    int tig = lid & 3;
    float lsum = 0.0f;

    bool interior = (it < 7) && (jt < 7);
    bool diag     = (it == jt);

    float xs[16];
    #pragma unroll
    for (int fm = 0; fm < 2; fm++)
        #pragma unroll
        for (int fn = 0; fn < 2; fn++)
            #pragma unroll
            for (int rg = 0; rg < 4; rg++)
                xs[fm * 8 + fn * 4 + rg] = acc[fm][fn][rg];

    if (interior && !diag) {
        float u[16], pc[16], lg[16];
        #pragma unroll
        for (int i = 0; i < 16; i++) u[i] = __expf(xs[i]);
        #pragma unroll
        for (int i = 0; i < 16; i++)
            pc[i] = fmaxf(__fdividef(1.0f, 1.0f + u[i]), PROB_MIN);
        #pragma unroll
        for (int i = 0; i < 16; i++) lg[i] = __logf(pc[i]);
        #pragma unroll
        for (int i = 0; i < 16; i++) {
            float omp = 1.0f - pc[i];
            lsum -= (1.0f - ALPHA) * omp * omp * lg[i];
        }
    } else {
        float wgt[16];
        bool  flip[16];
        #pragma unroll
        for (int fm = 0; fm < 2; fm++) {
            int ib = i0 + wm * 32 + fm * 16 + gid;
            int m0 = (diag && ib     < KK) ? mask[b * KK + ib]     : 0;
            int m8 = (diag && ib + 8 < KK) ? mask[b * KK + ib + 8] : 0;
            #pragma unroll
            for (int fn = 0; fn < 2; fn++) {
                int jb = j0 + wn * 16 + fn * 8 + 2 * tig;
                #pragma unroll
                for (int rg = 0; rg < 4; rg++) {
                    int i = ib + (rg >> 1) * 8;
                    int j = jb + (rg & 1);
                    int idx = fm * 8 + fn * 4 + rg;
                    bool inb = (i < KK) && (j < KK);
                    bool gt  = diag && (i == j) &&
                               (((rg >> 1) ? m8 : m0) != 0);
                    flip[idx] = gt;
                    wgt[idx]  = inb ? (gt ? ALPHA : (1.0f - ALPHA)) : 0.0f;
                }
            }
        }
        float u[16], pc[16], lg[16];
        #pragma unroll
        for (int i = 0; i < 16; i++) u[i] = __expf(xs[i]);
        #pragma unroll
        for (int i = 0; i < 16; i++) {
            float r = __fdividef(1.0f, 1.0f + u[i]);
            pc[i] = fmaxf(flip[i] ? (1.0f - r) : r, PROB_MIN);
        }
        #pragma unroll
        for (int i = 0; i < 16; i++) lg[i] = __logf(pc[i]);
        #pragma unroll
        for (int i = 0; i < 16; i++) {
            float omp = 1.0f - pc[i];
            lsum -= wgt[i] * omp * omp * lg[i];
        }
    }

    // Reduce + last-block finalize
    #pragma unroll
    for (int o = 16; o > 0; o >>= 1)
        lsum += __shfl_xor_sync(0xffffffffu, lsum, o);
    if (lid == 0) wsum[w] = lsum;
    __syncthreads();

    if (t == 0) {
        float v = 0.f;
        #pragma unroll
        for (int k = 0; k < 8; k++) v += wsum[k];
        int bid = blockIdx.x + 8 * blockIdx.y + 64 * blockIdx.z;
        atomicAdd(&g_accs[bid & (NSLOTS - 1)], (double)v);
        __threadfence();
        unsigned old = atomicAdd(&g_count, 1u);
        if (old == NLBLK - 1) {           // last block: finalize + reset
            double tot = 0.0;
            #pragma unroll
            for (int s = 0; s < NSLOTS; s++) {
                tot += g_accs[s];
                g_accs[s] = 0.0;
            }
            out[0] = (float)(tot / ((double)BB * KK * KK));
            __threadfence();
            g_count = 0u;
        }
    }
}

extern "C" void kernel_launch(void* const* d_in, const int* in_sizes, int n_in,
                              void* d_out, int out_size)
{
    const float* cur_reid = (const float*)d_in[0];
    const float* pre_reid = (const float*)d_in[1];
    const int*   mask     = (const int*)d_in[6];
    float* out = (float*)d_out;

    int totalPairs = BB * KPAD * 32;
    gather_kernel<<<(totalPairs + 255) / 256, 256>>>(cur_reid, pre_reid,
                                                     d_in[2], d_in[3],
                                                     d_in[4], d_in[5], mask);

    dim3 grid(8, 8, BB);
    loss_kernel<<<grid, 256>>>(mask, out);
}

// round 15
// speedup vs baseline: 1.1356x; 1.1356x over previous
#include <cuda_runtime.h>
#include <cuda_bf16.h>
#include <cstdint>

#define BB 8
#define CC 64
#define HWSZ (152 * 272)     // 41344
#define KK 500
#define KPAD 512
#define NSLOTS 128

#define ALPHA 0.25f
#define PROB_MIN 1e-4f

// Scratch (no allocations allowed)
__device__ __align__(16) __nv_bfloat16 g_curb[BB * KPAD * CC];
__device__ __align__(16) __nv_bfloat16 g_preb[BB * KPAD * CC];
__device__ double g_accs[NSLOTS];   // zero-init; finalize resets after reading

__device__ __forceinline__ uint32_t smem_u32(const void* p) {
    uint32_t a;
    asm("{ .reg .u64 t; cvta.to.shared.u64 t, %1; cvt.u32.u64 %0, t; }"
        : "=r"(a) : "l"(p));
    return a;
}
__device__ __forceinline__ void ldsm_x4(uint32_t& r0, uint32_t& r1,
                                        uint32_t& r2, uint32_t& r3,
                                        uint32_t addr) {
    asm volatile("ldmatrix.sync.aligned.m8n8.x4.shared.b16 {%0,%1,%2,%3}, [%4];"
                 : "=r"(r0), "=r"(r1), "=r"(r2), "=r"(r3) : "r"(addr));
}
__device__ __forceinline__ void ldsm_x2(uint32_t& r0, uint32_t& r1,
                                        uint32_t addr) {
    asm volatile("ldmatrix.sync.aligned.m8n8.x2.shared.b16 {%0,%1}, [%2];"
                 : "=r"(r0), "=r"(r1) : "r"(addr));
}
__device__ __forceinline__ void mma_16816(float* c, const uint32_t* a,
                                          const uint32_t* b) {
    asm volatile(
        "mma.sync.aligned.m16n8k16.row.col.f32.bf16.bf16.f32 "
        "{%0,%1,%2,%3}, {%4,%5,%6,%7}, {%8,%9}, {%0,%1,%2,%3};"
        : "+f"(c[0]), "+f"(c[1]), "+f"(c[2]), "+f"(c[3])
        : "r"(a[0]), "r"(a[1]), "r"(a[2]), "r"(a[3]), "r"(b[0]), "r"(b[1]));
}

// ---------------------------------------------------------------------------
// Gather + bf16 convert (round-7 body, reshaped to 512 blocks x 128 threads:
// identical per-thread work/memory pattern, lower block-imbalance tail for
// this latency-bound kernel). Inline int64/int32 index-dtype detection.
// ---------------------------------------------------------------------------
__global__ __launch_bounds__(128)
void gather_kernel(const float* __restrict__ cur_reid,
                   const float* __restrict__ pre_reid,
                   const void*  __restrict__ cur_inds,
                   const void*  __restrict__ pre_inds,
                   const void*  __restrict__ cur_cir,
                   const void*  __restrict__ pre_cir,
                   const int*   __restrict__ mask)
{
    __shared__ int s64;
    if (threadIdx.x < 32) {
        long long v = ((const long long*)cur_inds)[threadIdx.x];
        unsigned bad = __ballot_sync(0xffffffffu,
                                     (v < 0) || (v >= (long long)HWSZ));
        if (threadIdx.x == 0) s64 = (bad == 0);
    }
    __syncthreads();

    int tid = blockIdx.x * 128 + threadIdx.x;
    if (tid >= BB * KPAD * 16) return;
    int c4  = tid & 15;
    int bk  = tid >> 4;
    int b   = bk >> 9;
    int row = bk & (KPAD - 1);

    uint2* dstC = (uint2*)g_curb;
    uint2* dstP = (uint2*)g_preb;

    if (row >= KK) {
        uint2 z = make_uint2(0u, 0u);
        dstC[tid] = z;
        dstP[tid] = z;
        return;
    }
    int mk = b * KK + row;
    int m  = mask[mk];
    int ic, ip;
    if (s64) {
        ic = (int)(m ? ((const long long*)cur_inds)[mk]
                     : ((const long long*)cur_cir)[mk]);
        ip = (int)(m ? ((const long long*)pre_inds)[mk]
                     : ((const long long*)pre_cir)[mk]);
    } else {
        ic = m ? ((const int*)cur_inds)[mk] : ((const int*)cur_cir)[mk];
        ip = m ? ((const int*)pre_inds)[mk] : ((const int*)pre_cir)[mk];
    }
    size_t base = ((size_t)b * CC + 4 * c4) * (size_t)HWSZ;
    float c0 = cur_reid[base + ic];
    float c1 = cur_reid[base + HWSZ + ic];
    float c2 = cur_reid[base + 2 * (size_t)HWSZ + ic];
    float c3 = cur_reid[base + 3 * (size_t)HWSZ + ic];
    float p0 = pre_reid[base + ip];
    float p1 = pre_reid[base + HWSZ + ip];
    float p2 = pre_reid[base + 2 * (size_t)HWSZ + ip];
    float p3 = pre_reid[base + 3 * (size_t)HWSZ + ip];
    __nv_bfloat162 vc0, vc1, vp0, vp1;
    vc0.x = __float2bfloat16(c0); vc0.y = __float2bfloat16(c1);
    vc1.x = __float2bfloat16(c2); vc1.y = __float2bfloat16(c3);
    vp0.x = __float2bfloat16(p0); vp0.y = __float2bfloat16(p1);
    vp1.x = __float2bfloat16(p2); vp1.y = __float2bfloat16(p3);
    uint2 uc, up;
    uc.x = *(uint32_t*)&vc0; uc.y = *(uint32_t*)&vc1;
    up.x = *(uint32_t*)&vp0; up.y = *(uint32_t*)&vp1;
    dstC[tid] = uc;
    dstP[tid] = up;
}

// ---------------------------------------------------------------------------
// HMMA loss kernel (champion structure, breadth-first epilogue).
// 64x64 tile/block, grid (8,8,8)=512, 8 warps of 32x16 warp tiles.
// ---------------------------------------------------------------------------
__global__ __launch_bounds__(256)
void loss_kernel(const int* __restrict__ mask)
{
    __shared__ __align__(128) uint8_t smA[64 * 128];
    __shared__ __align__(128) uint8_t smB[64 * 128];
    __shared__ float wsum[8];

    int t   = threadIdx.x;
    int w   = t >> 5;
    int lid = t & 31;
    int b   = blockIdx.z;
    int it  = blockIdx.y;
    int jt  = blockIdx.x;
    int i0  = it * 64;
    int j0  = jt * 64;

    const uint4* srcA = (const uint4*)(g_curb + ((size_t)b * KPAD + i0) * CC);
    const uint4* srcB = (const uint4*)(g_preb + ((size_t)b * KPAD + j0) * CC);
    #pragma unroll
    for (int k = 0; k < 2; k++) {
        int u  = t + 256 * k;
        int r  = u >> 3;
        int c  = u & 7;
        int sw = (r << 7) + ((c ^ (r & 7)) << 4);
        *(uint4*)(smA + sw) = srcA[u];
        *(uint4*)(smB + sw) = srcB[u];
    }
    __syncthreads();

    uint32_t baseA = smem_u32(smA);
    uint32_t baseB = smem_u32(smB);

    int wm = w & 1;
    int wn = w >> 1;

    float acc[2][2][4] = {};
    #pragma unroll
    for (int ks = 0; ks < 4; ks++) {
        int kc = ks * 2;
        uint32_t a[2][4];
        #pragma unroll
        for (int fm = 0; fm < 2; fm++) {
            int row = wm * 32 + fm * 16 + (lid & 7) + ((lid >> 3) & 1) * 8;
            int ch  = kc + (lid >> 4);
            uint32_t addr = baseA + (row << 7) + ((ch ^ (row & 7)) << 4);
            ldsm_x4(a[fm][0], a[fm][1], a[fm][2], a[fm][3], addr);
        }
        uint32_t bf[2][2];
        #pragma unroll
        for (int fn = 0; fn < 2; fn++) {
            int l8  = lid & 15;
            int row = wn * 16 + fn * 8 + (l8 & 7);
            int ch  = kc + (l8 >> 3);
            uint32_t addr = baseB + (row << 7) + ((ch ^ (row & 7)) << 4);
            ldsm_x2(bf[fn][0], bf[fn][1], addr);
        }
        #pragma unroll
        for (int fm = 0; fm < 2; fm++)
            #pragma unroll
            for (int fn = 0; fn < 2; fn++)
                mma_16816(acc[fm][fn], a[fm], bf[fn]);
    }

    // ---------------- breadth-first epilogue ----------------
    int gid = lid >> 2;
    int tig = lid & 3;
    float lsum = 0.0f;

    bool interior = (it < 7) && (jt < 7);
    bool diag     = (it == jt);

    float xs[16];
    #pragma unroll
    for (int fm = 0; fm < 2; fm++)
        #pragma unroll
        for (int fn = 0; fn < 2; fn++)
            #pragma unroll
            for (int rg = 0; rg < 4; rg++)
                xs[fm * 8 + fn * 4 + rg] = acc[fm][fn][rg];

    if (interior && !diag) {
        float u[16], pc[16], lg[16];
        #pragma unroll
        for (int i = 0; i < 16; i++) u[i] = __expf(xs[i]);
        #pragma unroll
        for (int i = 0; i < 16; i++)
            pc[i] = fmaxf(__fdividef(1.0f, 1.0f + u[i]), PROB_MIN);
        #pragma unroll
        for (int i = 0; i < 16; i++) lg[i] = __logf(pc[i]);
        #pragma unroll
        for (int i = 0; i < 16; i++) {
            float omp = 1.0f - pc[i];
            lsum -= (1.0f - ALPHA) * omp * omp * lg[i];
        }
    } else {
        float wgt[16];
        bool  flip[16];
        #pragma unroll
        for (int fm = 0; fm < 2; fm++) {
            int ib = i0 + wm * 32 + fm * 16 + gid;
            int m0 = (diag && ib     < KK) ? mask[b * KK + ib]     : 0;
            int m8 = (diag && ib + 8 < KK) ? mask[b * KK + ib + 8] : 0;
            #pragma unroll
            for (int fn = 0; fn < 2; fn++) {
                int jb = j0 + wn * 16 + fn * 8 + 2 * tig;
                #pragma unroll
                for (int rg = 0; rg < 4; rg++) {
                    int i = ib + (rg >> 1) * 8;
                    int j = jb + (rg & 1);
                    int idx = fm * 8 + fn * 4 + rg;
                    bool inb = (i < KK) && (j < KK);
                    bool gt  = diag && (i == j) &&
                               (((rg >> 1) ? m8 : m0) != 0);
                    flip[idx] = gt;
                    wgt[idx]  = inb ? (gt ? ALPHA : (1.0f - ALPHA)) : 0.0f;
                }
            }
        }
        float u[16], pc[16], lg[16];
        #pragma unroll
        for (int i = 0; i < 16; i++) u[i] = __expf(xs[i]);
        #pragma unroll
        for (int i = 0; i < 16; i++) {
            float r = __fdividef(1.0f, 1.0f + u[i]);
            pc[i] = fmaxf(flip[i] ? (1.0f - r) : r, PROB_MIN);
        }
        #pragma unroll
        for (int i = 0; i < 16; i++) lg[i] = __logf(pc[i]);
        #pragma unroll
        for (int i = 0; i < 16; i++) {
            float omp = 1.0f - pc[i];
            lsum -= wgt[i] * omp * omp * lg[i];
        }
    }

    // Reduce -> spread slot
    #pragma unroll
    for (int o = 16; o > 0; o >>= 1)
        lsum += __shfl_xor_sync(0xffffffffu, lsum, o);
    if (lid == 0) wsum[w] = lsum;
    __syncthreads();

    if (t == 0) {
        float v = 0.f;
        #pragma unroll
        for (int k = 0; k < 8; k++) v += wsum[k];
        int bid = blockIdx.x + 8 * blockIdx.y + 64 * blockIdx.z;
        atomicAdd(&g_accs[bid & (NSLOTS - 1)], (double)v);
    }
}

// ---------------------------------------------------------------------------
// Finalize: sum the slots, write mean, reset slots (graph-replay safe).
// ---------------------------------------------------------------------------
__global__ void finalize_kernel(float* __restrict__ out)
{
    __shared__ double ssum[4];
    int t = threadIdx.x;          // 128 threads
    double v = g_accs[t];
    g_accs[t] = 0.0;
    #pragma unroll
    for (int o = 16; o > 0; o >>= 1)
        v += __shfl_xor_sync(0xffffffffu, v, o);
    if ((t & 31) == 0) ssum[t >> 5] = v;
    __syncthreads();
    if (t == 0) {
        double tot = ssum[0] + ssum[1] + ssum[2] + ssum[3];
        out[0] = (float)(tot / ((double)BB * KK * KK));
    }
}

extern "C" void kernel_launch(void* const* d_in, const int* in_sizes, int n_in,
                              void* d_out, int out_size)
{
    const float* cur_reid = (const float*)d_in[0];
    const float* pre_reid = (const float*)d_in[1];
    const int*   mask     = (const int*)d_in[6];
    float* out = (float*)d_out;

    int totalGroups = BB * KPAD * 16;                 // 65536
    gather_kernel<<<totalGroups / 128, 128>>>(cur_reid, pre_reid,
                                              d_in[2], d_in[3],
                                              d_in[4], d_in[5], mask);

    dim3 grid(8, 8, BB);
    loss_kernel<<<grid, 256>>>(mask);

    finalize_kernel<<<1, 128>>>(out);
}

// round 16
// speedup vs baseline: 1.1577x; 1.0194x over previous
#include <cuda_runtime.h>
#include <cuda_bf16.h>
#include <cstdint>

#define BB 8
#define CC 64
#define HWSZ (152 * 272)     // 41344
#define KK 500
#define KPAD 512
#define NSLOTS 128

#define ALPHA 0.25f
#define PROB_MIN 1e-4f

// Scratch (no allocations allowed)
__device__ __align__(16) __nv_bfloat16 g_curb[BB * KPAD * CC];
__device__ __align__(16) __nv_bfloat16 g_preb[BB * KPAD * CC];
__device__ double g_accs[NSLOTS];   // zero-init; finalize resets after reading

__device__ __forceinline__ uint32_t smem_u32(const void* p) {
    uint32_t a;
    asm("{ .reg .u64 t; cvta.to.shared.u64 t, %1; cvt.u32.u64 %0, t; }"
        : "=r"(a) : "l"(p));
    return a;
}
__device__ __forceinline__ void ldsm_x4(uint32_t& r0, uint32_t& r1,
                                        uint32_t& r2, uint32_t& r3,
                                        uint32_t addr) {
    asm volatile("ldmatrix.sync.aligned.m8n8.x4.shared.b16 {%0,%1,%2,%3}, [%4];"
                 : "=r"(r0), "=r"(r1), "=r"(r2), "=r"(r3) : "r"(addr));
}
__device__ __forceinline__ void ldsm_x2(uint32_t& r0, uint32_t& r1,
                                        uint32_t addr) {
    asm volatile("ldmatrix.sync.aligned.m8n8.x2.shared.b16 {%0,%1}, [%2];"
                 : "=r"(r0), "=r"(r1) : "r"(addr));
}
__device__ __forceinline__ void mma_16816(float* c, const uint32_t* a,
                                          const uint32_t* b) {
    asm volatile(
        "mma.sync.aligned.m16n8k16.row.col.f32.bf16.bf16.f32 "
        "{%0,%1,%2,%3}, {%4,%5,%6,%7}, {%8,%9}, {%0,%1,%2,%3};"
        : "+f"(c[0]), "+f"(c[1]), "+f"(c[2]), "+f"(c[3])
        : "r"(a[0]), "r"(a[1]), "r"(a[2]), "r"(a[3]), "r"(b[0]), "r"(b[1]));
}

// ---------------------------------------------------------------------------
// Gather + bf16 convert (proven round-7 version: 4 channels/thread, uint2
// stores, inline int64/int32 index-dtype detection).
// ---------------------------------------------------------------------------
__global__ __launch_bounds__(256)
void gather_kernel(const float* __restrict__ cur_reid,
                   const float* __restrict__ pre_reid,
                   const void*  __restrict__ cur_inds,
                   const void*  __restrict__ pre_inds,
                   const void*  __restrict__ cur_cir,
                   const void*  __restrict__ pre_cir,
                   const int*   __restrict__ mask)
{
    __shared__ int s64;
    if (threadIdx.x < 32) {
        long long v = ((const long long*)cur_inds)[threadIdx.x];
        unsigned bad = __ballot_sync(0xffffffffu,
                                     (v < 0) || (v >= (long long)HWSZ));
        if (threadIdx.x == 0) s64 = (bad == 0);
    }
    __syncthreads();

    int tid = blockIdx.x * 256 + threadIdx.x;
    if (tid >= BB * KPAD * 16) return;
    int c4  = tid & 15;
    int bk  = tid >> 4;
    int b   = bk >> 9;
    int row = bk & (KPAD - 1);

    uint2* dstC = (uint2*)g_curb;
    uint2* dstP = (uint2*)g_preb;

    if (row >= KK) {
        uint2 z = make_uint2(0u, 0u);
        dstC[tid] = z;
        dstP[tid] = z;
        return;
    }
    int mk = b * KK + row;
    int m  = mask[mk];
    int ic, ip;
    if (s64) {
        ic = (int)(m ? ((const long long*)cur_inds)[mk]
                     : ((const long long*)cur_cir)[mk]);
        ip = (int)(m ? ((const long long*)pre_inds)[mk]
                     : ((const long long*)pre_cir)[mk]);
    } else {
        ic = m ? ((const int*)cur_inds)[mk] : ((const int*)cur_cir)[mk];
        ip = m ? ((const int*)pre_inds)[mk] : ((const int*)pre_cir)[mk];
    }
    size_t base = ((size_t)b * CC + 4 * c4) * (size_t)HWSZ;
    float c0 = cur_reid[base + ic];
    float c1 = cur_reid[base + HWSZ + ic];
    float c2 = cur_reid[base + 2 * (size_t)HWSZ + ic];
    float c3 = cur_reid[base + 3 * (size_t)HWSZ + ic];
    float p0 = pre_reid[base + ip];
    float p1 = pre_reid[base + HWSZ + ip];
    float p2 = pre_reid[base + 2 * (size_t)HWSZ + ip];
    float p3 = pre_reid[base + 3 * (size_t)HWSZ + ip];
    __nv_bfloat162 vc0, vc1, vp0, vp1;
    vc0.x = __float2bfloat16(c0); vc0.y = __float2bfloat16(c1);
    vc1.x = __float2bfloat16(c2); vc1.y = __float2bfloat16(c3);
    vp0.x = __float2bfloat16(p0); vp0.y = __float2bfloat16(p1);
    vp1.x = __float2bfloat16(p2); vp1.y = __float2bfloat16(p3);
    uint2 uc, up;
    uc.x = *(uint32_t*)&vc0; uc.y = *(uint32_t*)&vc1;
    up.x = *(uint32_t*)&vp0; up.y = *(uint32_t*)&vp1;
    dstC[tid] = uc;
    dstP[tid] = up;
}

// ---------------------------------------------------------------------------
// HMMA loss kernel (champion structure, breadth-first epilogue).
// 64x64 tile/block, grid (8,8,8)=512, 8 warps of 32x16 warp tiles.
// ---------------------------------------------------------------------------
__global__ __launch_bounds__(256)
void loss_kernel(const int* __restrict__ mask)
{
    __shared__ __align__(128) uint8_t smA[64 * 128];
    __shared__ __align__(128) uint8_t smB[64 * 128];
    __shared__ float wsum[8];

    int t   = threadIdx.x;
    int w   = t >> 5;
    int lid = t & 31;
    int b   = blockIdx.z;
    int it  = blockIdx.y;
    int jt  = blockIdx.x;
    int i0  = it * 64;
    int j0  = jt * 64;

    const uint4* srcA = (const uint4*)(g_curb + ((size_t)b * KPAD + i0) * CC);
    const uint4* srcB = (const uint4*)(g_preb + ((size_t)b * KPAD + j0) * CC);
    #pragma unroll
    for (int k = 0; k < 2; k++) {
        int u  = t + 256 * k;
        int r  = u >> 3;
        int c  = u & 7;
        int sw = (r << 7) + ((c ^ (r & 7)) << 4);
        *(uint4*)(smA + sw) = srcA[u];
        *(uint4*)(smB + sw) = srcB[u];
    }
    __syncthreads();

    uint32_t baseA = smem_u32(smA);
    uint32_t baseB = smem_u32(smB);

    int wm = w & 1;
    int wn = w >> 1;

    float acc[2][2][4] = {};
    #pragma unroll
    for (int ks = 0; ks < 4; ks++) {
        int kc = ks * 2;
        uint32_t a[2][4];
        #pragma unroll
        for (int fm = 0; fm < 2; fm++) {
            int row = wm * 32 + fm * 16 + (lid & 7) + ((lid >> 3) & 1) * 8;
            int ch  = kc + (lid >> 4);
            uint32_t addr = baseA + (row << 7) + ((ch ^ (row & 7)) << 4);
            ldsm_x4(a[fm][0], a[fm][1], a[fm][2], a[fm][3], addr);
        }
        uint32_t bf[2][2];
        #pragma unroll
        for (int fn = 0; fn < 2; fn++) {
            int l8  = lid & 15;
            int row = wn * 16 + fn * 8 + (l8 & 7);
            int ch  = kc + (l8 >> 3);
            uint32_t addr = baseB + (row << 7) + ((ch ^ (row & 7)) << 4);
            ldsm_x2(bf[fn][0], bf[fn][1], addr);
        }
        #pragma unroll
        for (int fm = 0; fm < 2; fm++)
            #pragma unroll
            for (int fn = 0; fn < 2; fn++)
                mma_16816(acc[fm][fn], a[fm], bf[fn]);
    }

    // ---------------- breadth-first epilogue ----------------
    int gid = lid >> 2;
    int tig = lid & 3;
    float lsum = 0.0f;

    bool interior = (it < 7) && (jt < 7);
    bool diag     = (it == jt);

    float xs[16];
    #pragma unroll
    for (int fm = 0; fm < 2; fm++)
        #pragma unroll
        for (int fn = 0; fn < 2; fn++)
            #pragma unroll
            for (int rg = 0; rg < 4; rg++)
                xs[fm * 8 + fn * 4 + rg] = acc[fm][fn][rg];

    if (interior && !diag) {
        float u[16], pc[16], lg[16];
        #pragma unroll
        for (int i = 0; i < 16; i++) u[i] = __expf(xs[i]);
        #pragma unroll
        for (int i = 0; i < 16; i++)
            pc[i] = fmaxf(__fdividef(1.0f, 1.0f + u[i]), PROB_MIN);
        #pragma unroll
        for (int i = 0; i < 16; i++) lg[i] = __logf(pc[i]);
        #pragma unroll
        for (int i = 0; i < 16; i++) {
            float omp = 1.0f - pc[i];
            lsum -= (1.0f - ALPHA) * omp * omp * lg[i];
        }
    } else {
        float wgt[16];
        bool  flip[16];
        #pragma unroll
        for (int fm = 0; fm < 2; fm++) {
            int ib = i0 + wm * 32 + fm * 16 + gid;
            int m0 = (diag && ib     < KK) ? mask[b * KK + ib]     : 0;
            int m8 = (diag && ib + 8 < KK) ? mask[b * KK + ib + 8] : 0;
            #pragma unroll
            for (int fn = 0; fn < 2; fn++) {
                int jb = j0 + wn * 16 + fn * 8 + 2 * tig;
                #pragma unroll
                for (int rg = 0; rg < 4; rg++) {
                    int i = ib + (rg >> 1) * 8;
                    int j = jb + (rg & 1);
                    int idx = fm * 8 + fn * 4 + rg;
                    bool inb = (i < KK) && (j < KK);
                    bool gt  = diag && (i == j) &&
                               (((rg >> 1) ? m8 : m0) != 0);
                    flip[idx] = gt;
                    wgt[idx]  = inb ? (gt ? ALPHA : (1.0f - ALPHA)) : 0.0f;
                }
            }
        }
        float u[16], pc[16], lg[16];
        #pragma unroll
        for (int i = 0; i < 16; i++) u[i] = __expf(xs[i]);
        #pragma unroll
        for (int i = 0; i < 16; i++) {
            float r = __fdividef(1.0f, 1.0f + u[i]);
            pc[i] = fmaxf(flip[i] ? (1.0f - r) : r, PROB_MIN);
        }
        #pragma unroll
        for (int i = 0; i < 16; i++) lg[i] = __logf(pc[i]);
        #pragma unroll
        for (int i = 0; i < 16; i++) {
            float omp = 1.0f - pc[i];
            lsum -= wgt[i] * omp * omp * lg[i];
        }
    }

    // Reduce -> spread slot
    #pragma unroll
    for (int o = 16; o > 0; o >>= 1)
        lsum += __shfl_xor_sync(0xffffffffu, lsum, o);
    if (lid == 0) wsum[w] = lsum;
    __syncthreads();

    if (t == 0) {
        float v = 0.f;
        #pragma unroll
        for (int k = 0; k < 8; k++) v += wsum[k];
        int bid = blockIdx.x + 8 * blockIdx.y + 64 * blockIdx.z;
        atomicAdd(&g_accs[bid & (NSLOTS - 1)], (double)v);
    }
}

// ---------------------------------------------------------------------------
// Finalize: sum the slots, write mean, reset slots (graph-replay safe).
// ---------------------------------------------------------------------------
__global__ void finalize_kernel(float* __restrict__ out)
{
    __shared__ double ssum[4];
    int t = threadIdx.x;          // 128 threads
    double v = g_accs[t];
    g_accs[t] = 0.0;
    #pragma unroll
    for (int o = 16; o > 0; o >>= 1)
        v += __shfl_xor_sync(0xffffffffu, v, o);
    if ((t & 31) == 0) ssum[t >> 5] = v;
    __syncthreads();
    if (t == 0) {
        double tot = ssum[0] + ssum[1] + ssum[2] + ssum[3];
        out[0] = (float)(tot / ((double)BB * KK * KK));
    }
}

extern "C" void kernel_launch(void* const* d_in, const int* in_sizes, int n_in,
                              void* d_out, int out_size)
{
    const float* cur_reid = (const float*)d_in[0];
    const float* pre_reid = (const float*)d_in[1];
    const int*   mask     = (const int*)d_in[6];
    float* out = (float*)d_out;

    int totalGroups = BB * KPAD * 16;
    gather_kernel<<<(totalGroups + 255) / 256, 256>>>(cur_reid, pre_reid,
                                                      d_in[2], d_in[3],
                                                      d_in[4], d_in[5], mask);

    dim3 grid(8, 8, BB);
    loss_kernel<<<grid, 256>>>(mask);

    finalize_kernel<<<1, 128>>>(out);
}